// round 1
// baseline (speedup 1.0000x reference)
#include <cuda_runtime.h>
#include <math.h>

// Problem constants
#define B_   32
#define Q_   20
#define T_   100
#define D_   512
#define H_   512
#define N_   (B_*Q_)        // 640 sequences
#define G_   (4*H_)         // 2048 gate columns
#define M_   (N_*T_)        // 64000 rows of the x_gates GEMM

// Scratch (static device globals — no runtime allocation)
__device__ float g_xg[(size_t)M_ * G_];   // [n][t][4H] precomputed input gates (+bias)
__device__ float g_h[2][N_ * H_];         // ping-pong hidden state
__device__ float g_c[N_ * H_];            // cell state (updated in place)

// ---------------------------------------------------------------------------
// Kernel 0: zero h0 and c
// ---------------------------------------------------------------------------
__global__ void init_state_kernel() {
    int idx = blockIdx.x * blockDim.x + threadIdx.x;
    if (idx < N_ * H_) {
        g_h[0][idx] = 0.0f;
        g_c[idx]    = 0.0f;
    }
}

// ---------------------------------------------------------------------------
// Kernel 1: x_gates GEMM.  C[m,j] = sum_k X[m,k] * Wih[j,k] + (bih[j]+bhh[j])
// X is [M, 512] row-major (m = n*T + t), Wih is [2048, 512] row-major.
// 128x128 block tile, BK=16, 256 threads, 8x8 per-thread micro-tile.
// ---------------------------------------------------------------------------
#define BM 128
#define BN 128
#define BK 16

__global__ __launch_bounds__(256) void xg_gemm_kernel(
    const float* __restrict__ X,
    const float* __restrict__ Wih,
    const float* __restrict__ bih,
    const float* __restrict__ bhh)
{
    __shared__ float As[BK][BM];
    __shared__ float Bs[BK][BN];

    const int tid = threadIdx.x;
    const int bm  = blockIdx.y * BM;
    const int bj  = blockIdx.x * BN;
    const int tx  = tid % 16;      // column group
    const int ty  = tid / 16;      // row group

    const int lr = tid / 4;        // 0..63 (load row)
    const int lk = (tid % 4) * 4;  // 0,4,8,12 (load k offset)

    float acc[8][8];
    #pragma unroll
    for (int i = 0; i < 8; ++i)
        #pragma unroll
        for (int j = 0; j < 8; ++j) acc[i][j] = 0.0f;

    const float* Aptr = X   + (size_t)bm * D_;
    const float* Bptr = Wih + (size_t)bj * D_;

    for (int kt = 0; kt < D_; kt += BK) {
        #pragma unroll
        for (int s = 0; s < 2; ++s) {
            int r = lr + s * 64;
            float4 v = *(const float4*)(Aptr + (size_t)r * D_ + kt + lk);
            As[lk + 0][r] = v.x; As[lk + 1][r] = v.y;
            As[lk + 2][r] = v.z; As[lk + 3][r] = v.w;
        }
        #pragma unroll
        for (int s = 0; s < 2; ++s) {
            int r = lr + s * 64;
            float4 v = *(const float4*)(Bptr + (size_t)r * D_ + kt + lk);
            Bs[lk + 0][r] = v.x; Bs[lk + 1][r] = v.y;
            Bs[lk + 2][r] = v.z; Bs[lk + 3][r] = v.w;
        }
        __syncthreads();

        #pragma unroll
        for (int k = 0; k < BK; ++k) {
            float a[8], b[8];
            *(float4*)(a)     = *(const float4*)&As[k][ty * 4];
            *(float4*)(a + 4) = *(const float4*)&As[k][ty * 4 + 64];
            *(float4*)(b)     = *(const float4*)&Bs[k][tx * 4];
            *(float4*)(b + 4) = *(const float4*)&Bs[k][tx * 4 + 64];
            #pragma unroll
            for (int i = 0; i < 8; ++i)
                #pragma unroll
                for (int j = 0; j < 8; ++j)
                    acc[i][j] += a[i] * b[j];
        }
        __syncthreads();
    }

    // bias per owned column
    float bsum[8];
    #pragma unroll
    for (int j = 0; j < 8; ++j) {
        int c = bj + ((j < 4) ? tx * 4 + j : 64 + tx * 4 + (j - 4));
        bsum[j] = bih[c] + bhh[c];
    }

    #pragma unroll
    for (int i = 0; i < 8; ++i) {
        int m = bm + ((i < 4) ? ty * 4 + i : 64 + ty * 4 + (i - 4));
        float* crow = g_xg + (size_t)m * G_ + bj;
        float4 o0, o1;
        o0.x = acc[i][0] + bsum[0]; o0.y = acc[i][1] + bsum[1];
        o0.z = acc[i][2] + bsum[2]; o0.w = acc[i][3] + bsum[3];
        o1.x = acc[i][4] + bsum[4]; o1.y = acc[i][5] + bsum[5];
        o1.z = acc[i][6] + bsum[6]; o1.w = acc[i][7] + bsum[7];
        *(float4*)(crow + tx * 4)      = o0;
        *(float4*)(crow + 64 + tx * 4) = o1;
    }
}

// ---------------------------------------------------------------------------
// Kernel 2: one LSTM timestep, fused recurrent GEMM + cell update.
// Block tile: 64 rows (n) x 32 hidden cols -> 128 gate cols (i,f,g,o of the
// same 32 h-columns), so each thread owns all 4 gates of its (n,h) pairs.
// grid = (H/32=16, N/64=10), 256 threads (tx=h lane, wy=row group of 8).
// ---------------------------------------------------------------------------
#define SBK 16

__global__ __launch_bounds__(256) void lstm_step_kernel(
    const float* __restrict__ Whh,
    float* __restrict__ out,     // d_out, used only at t == T-1
    int t)
{
    __shared__ float Hs[SBK][64];
    __shared__ float Ws[SBK][128];

    const float* h_in = g_h[t & 1];
    float* h_out = (t == T_ - 1) ? out : g_h[(t + 1) & 1];

    const int tid = threadIdx.x;
    const int bh  = blockIdx.x * 32;
    const int bn  = blockIdx.y * 64;
    const int tx  = tid & 31;    // h lane
    const int wy  = tid >> 5;    // 0..7 row group

    const int lr = tid / 4;        // 0..63
    const int lk = (tid % 4) * 4;  // 0,4,8,12

    float acc[8][4];
    #pragma unroll
    for (int i = 0; i < 8; ++i)
        #pragma unroll
        for (int g = 0; g < 4; ++g) acc[i][g] = 0.0f;

    for (int kt = 0; kt < H_; kt += SBK) {
        {
            float4 v = *(const float4*)(h_in + (size_t)(bn + lr) * H_ + kt + lk);
            Hs[lk + 0][lr] = v.x; Hs[lk + 1][lr] = v.y;
            Hs[lk + 2][lr] = v.z; Hs[lk + 3][lr] = v.w;
        }
        #pragma unroll
        for (int s = 0; s < 2; ++s) {
            int col  = lr + s * 64;          // 0..127
            int gate = col >> 5;             // 0..3
            int hl   = col & 31;
            int j    = gate * H_ + bh + hl;  // row of W_hh
            float4 v = *(const float4*)(Whh + (size_t)j * H_ + kt + lk);
            Ws[lk + 0][col] = v.x; Ws[lk + 1][col] = v.y;
            Ws[lk + 2][col] = v.z; Ws[lk + 3][col] = v.w;
        }
        __syncthreads();

        #pragma unroll
        for (int k = 0; k < SBK; ++k) {
            float w0 = Ws[k][tx];
            float w1 = Ws[k][32 + tx];
            float w2 = Ws[k][64 + tx];
            float w3 = Ws[k][96 + tx];
            #pragma unroll
            for (int i = 0; i < 8; ++i) {
                float hv = Hs[k][wy * 8 + i];
                acc[i][0] += hv * w0;
                acc[i][1] += hv * w1;
                acc[i][2] += hv * w2;
                acc[i][3] += hv * w3;
            }
        }
        __syncthreads();
    }

    const int h = bh + tx;
    #pragma unroll
    for (int i = 0; i < 8; ++i) {
        int n = bn + wy * 8 + i;
        const float* xg = g_xg + ((size_t)n * T_ + t) * G_;
        float ig = acc[i][0] + xg[h];
        float fg = acc[i][1] + xg[H_ + h];
        float gg = acc[i][2] + xg[2 * H_ + h];
        float og = acc[i][3] + xg[3 * H_ + h];

        float is = 1.0f / (1.0f + expf(-ig));
        float fs = 1.0f / (1.0f + expf(-fg));
        float gt = tanhf(gg);
        float os = 1.0f / (1.0f + expf(-og));

        size_t ci = (size_t)n * H_ + h;
        float c = fs * g_c[ci] + is * gt;
        g_c[ci] = c;
        h_out[ci] = os * tanhf(c);
    }
}

// ---------------------------------------------------------------------------
// Launch: init, big x_gates GEMM, then 100 fused recurrent steps.
// ---------------------------------------------------------------------------
extern "C" void kernel_launch(void* const* d_in, const int* in_sizes, int n_in,
                              void* d_out, int out_size)
{
    const float* X   = (const float*)d_in[0];   // [B,Q,T,D] == [N, T, D]
    const float* Wih = (const float*)d_in[1];   // [4H, D]
    const float* Whh = (const float*)d_in[2];   // [4H, H]
    const float* bih = (const float*)d_in[3];   // [4H]
    const float* bhh = (const float*)d_in[4];   // [4H]
    float* out = (float*)d_out;                 // [B,Q,H] == [N, H]

    init_state_kernel<<<(N_ * H_ + 255) / 256, 256>>>();

    dim3 ggrid(G_ / BN, M_ / BM);   // (16, 500)
    xg_gemm_kernel<<<ggrid, 256>>>(X, Wih, bih, bhh);

    dim3 sgrid(H_ / 32, N_ / 64);   // (16, 10)
    for (int t = 0; t < T_; ++t) {
        lstm_step_kernel<<<sgrid, 256>>>(Whh, out, t);
    }
}

// round 2
// speedup vs baseline: 1.0483x; 1.0483x over previous
#include <cuda_runtime.h>
#include <math.h>

// Problem constants
#define B_   32
#define Q_   20
#define T_   100
#define D_   512
#define H_   512
#define N_   (B_*Q_)        // 640 sequences
#define G_   (4*H_)         // 2048 gate columns
#define M_   (N_*T_)        // 64000 rows of the x_gates GEMM

// Scratch (static device globals — no runtime allocation)
__device__ float g_xg[(size_t)M_ * G_];   // [n][t][4H] precomputed input gates (+bias)
__device__ float g_h[2][N_ * H_];         // ping-pong hidden state
__device__ float g_c[N_ * H_];            // cell state (updated in place)

// ---------------------------------------------------------------------------
// Kernel 0: zero h0 and c
// ---------------------------------------------------------------------------
__global__ void init_state_kernel() {
    int idx = blockIdx.x * blockDim.x + threadIdx.x;
    if (idx < N_ * H_) {
        g_h[0][idx] = 0.0f;
        g_c[idx]    = 0.0f;
    }
}

// ---------------------------------------------------------------------------
// Kernel 1: x_gates GEMM (unchanged from R1 — runs at ~86% of fp32 peak).
// ---------------------------------------------------------------------------
#define BM 128
#define BN 128
#define BK 16

__global__ __launch_bounds__(256) void xg_gemm_kernel(
    const float* __restrict__ X,
    const float* __restrict__ Wih,
    const float* __restrict__ bih,
    const float* __restrict__ bhh)
{
    __shared__ float As[BK][BM];
    __shared__ float Bs[BK][BN];

    const int tid = threadIdx.x;
    const int bm  = blockIdx.y * BM;
    const int bj  = blockIdx.x * BN;
    const int tx  = tid % 16;
    const int ty  = tid / 16;

    const int lr = tid / 4;
    const int lk = (tid % 4) * 4;

    float acc[8][8];
    #pragma unroll
    for (int i = 0; i < 8; ++i)
        #pragma unroll
        for (int j = 0; j < 8; ++j) acc[i][j] = 0.0f;

    const float* Aptr = X   + (size_t)bm * D_;
    const float* Bptr = Wih + (size_t)bj * D_;

    for (int kt = 0; kt < D_; kt += BK) {
        #pragma unroll
        for (int s = 0; s < 2; ++s) {
            int r = lr + s * 64;
            float4 v = *(const float4*)(Aptr + (size_t)r * D_ + kt + lk);
            As[lk + 0][r] = v.x; As[lk + 1][r] = v.y;
            As[lk + 2][r] = v.z; As[lk + 3][r] = v.w;
        }
        #pragma unroll
        for (int s = 0; s < 2; ++s) {
            int r = lr + s * 64;
            float4 v = *(const float4*)(Bptr + (size_t)r * D_ + kt + lk);
            Bs[lk + 0][r] = v.x; Bs[lk + 1][r] = v.y;
            Bs[lk + 2][r] = v.z; Bs[lk + 3][r] = v.w;
        }
        __syncthreads();

        #pragma unroll
        for (int k = 0; k < BK; ++k) {
            float a[8], b[8];
            *(float4*)(a)     = *(const float4*)&As[k][ty * 4];
            *(float4*)(a + 4) = *(const float4*)&As[k][ty * 4 + 64];
            *(float4*)(b)     = *(const float4*)&Bs[k][tx * 4];
            *(float4*)(b + 4) = *(const float4*)&Bs[k][tx * 4 + 64];
            #pragma unroll
            for (int i = 0; i < 8; ++i)
                #pragma unroll
                for (int j = 0; j < 8; ++j)
                    acc[i][j] += a[i] * b[j];
        }
        __syncthreads();
    }

    float bsum[8];
    #pragma unroll
    for (int j = 0; j < 8; ++j) {
        int c = bj + ((j < 4) ? tx * 4 + j : 64 + tx * 4 + (j - 4));
        bsum[j] = bih[c] + bhh[c];
    }

    #pragma unroll
    for (int i = 0; i < 8; ++i) {
        int m = bm + ((i < 4) ? ty * 4 + i : 64 + ty * 4 + (i - 4));
        float* crow = g_xg + (size_t)m * G_ + bj;
        float4 o0, o1;
        o0.x = acc[i][0] + bsum[0]; o0.y = acc[i][1] + bsum[1];
        o0.z = acc[i][2] + bsum[2]; o0.w = acc[i][3] + bsum[3];
        o1.x = acc[i][4] + bsum[4]; o1.y = acc[i][5] + bsum[5];
        o1.z = acc[i][6] + bsum[6]; o1.w = acc[i][7] + bsum[7];
        *(float4*)(crow + tx * 4)      = o0;
        *(float4*)(crow + 64 + tx * 4) = o1;
    }
}

// ---------------------------------------------------------------------------
// Kernel 2: one LSTM timestep, fused recurrent GEMM + cell update.
// Tile: 64 n-rows x 32 h-cols (=128 gate cols). 256 threads.
// Double-buffered SMEM, BK=32 (16 stages, 1 sync/stage).
// Weight smem layout: Ws[k][hl*4 + gate] (stride 132) -> inner loop is
// 1x LDS.128 (4 gate weights) + 2x LDS.128 (broadcast Hs) + 32 FFMA per k.
// ---------------------------------------------------------------------------
#define SBK 32
#define NSTAGE (H_ / SBK)          // 16
#define WS_STRIDE 132              // 128 + 4 pad (breaks store bank conflicts)

__global__ __launch_bounds__(256) void lstm_step_kernel(
    const float* __restrict__ Whh,
    float* __restrict__ out,       // d_out, used only at t == T-1
    int t)
{
    __shared__ float Hs[2][SBK][64];
    __shared__ float Ws[2][SBK * WS_STRIDE];

    const float* h_in = g_h[t & 1];
    float* h_out = (t == T_ - 1) ? out : g_h[(t + 1) & 1];

    const int tid = threadIdx.x;
    const int bh  = blockIdx.x * 32;
    const int bn  = blockIdx.y * 64;
    const int tx  = tid & 31;      // h lane
    const int wy  = tid >> 5;      // 0..7 row group

    // --- loader mappings ---
    // Hs: each thread loads 2 float4 along k for one row.
    const int hr = tid & 63;            // row 0..63
    const int hk = (tid >> 6) * 4;      // k offset 0,4,8,12 (plus +16)
    // Ws: each thread loads 4 float4 along k for one gate column.
    const int wcol  = tid >> 1;         // 0..127
    const int wgate = wcol >> 5;        // 0..3
    const int whl   = wcol & 31;        // 0..31
    const int wk    = (tid & 1) * 4;    // 0 or 4
    const float* wrow = Whh + (size_t)(wgate * H_ + bh + whl) * H_;
    const float* hrow = h_in + (size_t)(bn + hr) * H_;

    float acc[8][4];
    #pragma unroll
    for (int i = 0; i < 8; ++i)
        #pragma unroll
        for (int g = 0; g < 4; ++g) acc[i][g] = 0.0f;

    float4 hbuf0, hbuf1, wbuf[4];

    // prefetch stage 0
    hbuf0 = *(const float4*)(hrow + hk);
    hbuf1 = *(const float4*)(hrow + hk + 16);
    #pragma unroll
    for (int c = 0; c < 4; ++c)
        wbuf[c] = *(const float4*)(wrow + wk + 8 * c);

    // store stage 0 into buffer 0
    {
        Hs[0][hk + 0][hr] = hbuf0.x; Hs[0][hk + 1][hr] = hbuf0.y;
        Hs[0][hk + 2][hr] = hbuf0.z; Hs[0][hk + 3][hr] = hbuf0.w;
        Hs[0][hk + 16][hr] = hbuf1.x; Hs[0][hk + 17][hr] = hbuf1.y;
        Hs[0][hk + 18][hr] = hbuf1.z; Hs[0][hk + 19][hr] = hbuf1.w;
        #pragma unroll
        for (int c = 0; c < 4; ++c) {
            int kb = wk + 8 * c;
            int off = whl * 4 + wgate;
            Ws[0][(kb + 0) * WS_STRIDE + off] = wbuf[c].x;
            Ws[0][(kb + 1) * WS_STRIDE + off] = wbuf[c].y;
            Ws[0][(kb + 2) * WS_STRIDE + off] = wbuf[c].z;
            Ws[0][(kb + 3) * WS_STRIDE + off] = wbuf[c].w;
        }
    }
    __syncthreads();

    int buf = 0;
    #pragma unroll 1
    for (int s = 0; s < NSTAGE; ++s) {
        // prefetch next stage (gmem -> regs) before compute
        if (s + 1 < NSTAGE) {
            int kt = (s + 1) * SBK;
            hbuf0 = *(const float4*)(hrow + kt + hk);
            hbuf1 = *(const float4*)(hrow + kt + hk + 16);
            #pragma unroll
            for (int c = 0; c < 4; ++c)
                wbuf[c] = *(const float4*)(wrow + kt + wk + 8 * c);
        }

        // compute current stage
        #pragma unroll
        for (int k = 0; k < SBK; ++k) {
            float a[8];
            *(float4*)(a)     = *(const float4*)&Hs[buf][k][wy * 8];
            *(float4*)(a + 4) = *(const float4*)&Hs[buf][k][wy * 8 + 4];
            float4 w = *(const float4*)&Ws[buf][k * WS_STRIDE + tx * 4];
            #pragma unroll
            for (int i = 0; i < 8; ++i) {
                acc[i][0] += a[i] * w.x;
                acc[i][1] += a[i] * w.y;
                acc[i][2] += a[i] * w.z;
                acc[i][3] += a[i] * w.w;
            }
        }

        // store next stage into the other buffer
        if (s + 1 < NSTAGE) {
            int nb = buf ^ 1;
            Hs[nb][hk + 0][hr] = hbuf0.x; Hs[nb][hk + 1][hr] = hbuf0.y;
            Hs[nb][hk + 2][hr] = hbuf0.z; Hs[nb][hk + 3][hr] = hbuf0.w;
            Hs[nb][hk + 16][hr] = hbuf1.x; Hs[nb][hk + 17][hr] = hbuf1.y;
            Hs[nb][hk + 18][hr] = hbuf1.z; Hs[nb][hk + 19][hr] = hbuf1.w;
            #pragma unroll
            for (int c = 0; c < 4; ++c) {
                int kb = wk + 8 * c;
                int off = whl * 4 + wgate;
                Ws[nb][(kb + 0) * WS_STRIDE + off] = wbuf[c].x;
                Ws[nb][(kb + 1) * WS_STRIDE + off] = wbuf[c].y;
                Ws[nb][(kb + 2) * WS_STRIDE + off] = wbuf[c].z;
                Ws[nb][(kb + 3) * WS_STRIDE + off] = wbuf[c].w;
            }
            __syncthreads();
        }
        buf ^= 1;
    }

    // epilogue: gate nonlinearities + cell/hidden update
    const int h = bh + tx;
    #pragma unroll
    for (int i = 0; i < 8; ++i) {
        int n = bn + wy * 8 + i;
        const float* xg = g_xg + ((size_t)n * T_ + t) * G_;
        float ig = acc[i][0] + xg[h];
        float fg = acc[i][1] + xg[H_ + h];
        float gg = acc[i][2] + xg[2 * H_ + h];
        float og = acc[i][3] + xg[3 * H_ + h];

        float is = 1.0f / (1.0f + expf(-ig));
        float fs = 1.0f / (1.0f + expf(-fg));
        float gt = tanhf(gg);
        float os = 1.0f / (1.0f + expf(-og));

        size_t ci = (size_t)n * H_ + h;
        float c = fs * g_c[ci] + is * gt;
        g_c[ci] = c;
        h_out[ci] = os * tanhf(c);
    }
}

// ---------------------------------------------------------------------------
// Launch: init, big x_gates GEMM, then 100 fused recurrent steps.
// ---------------------------------------------------------------------------
extern "C" void kernel_launch(void* const* d_in, const int* in_sizes, int n_in,
                              void* d_out, int out_size)
{
    const float* X   = (const float*)d_in[0];   // [B,Q,T,D] == [N, T, D]
    const float* Wih = (const float*)d_in[1];   // [4H, D]
    const float* Whh = (const float*)d_in[2];   // [4H, H]
    const float* bih = (const float*)d_in[3];   // [4H]
    const float* bhh = (const float*)d_in[4];   // [4H]
    float* out = (float*)d_out;                 // [B,Q,H] == [N, H]

    init_state_kernel<<<(N_ * H_ + 255) / 256, 256>>>();

    dim3 ggrid(G_ / BN, M_ / BM);   // (16, 500)
    xg_gemm_kernel<<<ggrid, 256>>>(X, Wih, bih, bhh);

    dim3 sgrid(H_ / 32, N_ / 64);   // (16, 10)
    for (int t = 0; t < T_; ++t) {
        lstm_step_kernel<<<sgrid, 256>>>(Whh, out, t);
    }
}

// round 4
// speedup vs baseline: 2.3466x; 2.2385x over previous
#include <cuda_runtime.h>
#include <cuda_fp16.h>
#include <stdint.h>
#include <math.h>

// Problem constants
#define B_   32
#define Q_   20
#define T_   100
#define KDIM 512          // D == H == 512 (GEMM K dim)
#define H_   512
#define N_   (B_*Q_)      // 640 sequences
#define G_   (4*H_)       // 2048 gate columns (interleaved: jp = h*4 + gate)
#define M_   (N_*T_)      // 64000 rows of the x_gates GEMM

#define LDS_   40         // padded smem row stride (fp16 elems): conflict-free ldmatrix
#define CH     32         // k-chunk
#define NCHUNK (KDIM/CH)  // 16

// ---------------------------------------------------------------------------
// Static device scratch
// ---------------------------------------------------------------------------
__device__ __align__(16) float  g_xg[(size_t)M_ * G_];      // interleaved gate pre-acts (fp32)
__device__ __align__(16) __half gX_hi[(size_t)M_ * KDIM];
__device__ __align__(16) __half gX_lo[(size_t)M_ * KDIM];
__device__ __align__(16) __half gWih_hi[(size_t)G_ * KDIM]; // interleaved rows
__device__ __align__(16) __half gWih_lo[(size_t)G_ * KDIM];
__device__ __align__(16) __half gWhh_hi[(size_t)G_ * KDIM]; // interleaved rows
__device__ __align__(16) __half gWhh_lo[(size_t)G_ * KDIM];
__device__ float g_biasI[G_];                               // interleaved bih+bhh
__device__ __align__(16) __half g_h_hi[2][(size_t)N_ * H_];
__device__ __align__(16) __half g_h_lo[2][(size_t)N_ * H_];
__device__ float g_c[(size_t)N_ * H_];

// ---------------------------------------------------------------------------
// PTX helpers (baseline compute_103-safe: cp.async / ldmatrix / mma.sync)
// ---------------------------------------------------------------------------
__device__ __forceinline__ uint32_t smem_u32_of(const void* p) {
    uint32_t a;
    asm("{ .reg .u64 t; cvta.to.shared.u64 t, %1; cvt.u32.u64 %0, t; }" : "=r"(a) : "l"(p));
    return a;
}

__device__ __forceinline__ void cp16(uint32_t dst, const void* src) {
    asm volatile("cp.async.cg.shared.global [%0], [%1], 16;" :: "r"(dst), "l"(src));
}
__device__ __forceinline__ void cp_commit() {
    asm volatile("cp.async.commit_group;" ::: "memory");
}
template<int NN> __device__ __forceinline__ void cp_wait() {
    asm volatile("cp.async.wait_group %0;" :: "n"(NN) : "memory");
}

__device__ __forceinline__ void ldm4(uint32_t addr, uint32_t* r) {
    asm volatile("ldmatrix.sync.aligned.m8n8.x4.shared.b16 {%0,%1,%2,%3}, [%4];"
        : "=r"(r[0]), "=r"(r[1]), "=r"(r[2]), "=r"(r[3]) : "r"(addr));
}

__device__ __forceinline__ void mma16816(float* c, const uint32_t* a, const uint32_t* b) {
    asm volatile("mma.sync.aligned.m16n8k16.row.col.f32.f16.f16.f32 "
        "{%0,%1,%2,%3}, {%4,%5,%6,%7}, {%8,%9}, {%0,%1,%2,%3};"
        : "+f"(c[0]), "+f"(c[1]), "+f"(c[2]), "+f"(c[3])
        : "r"(a[0]), "r"(a[1]), "r"(a[2]), "r"(a[3]), "r"(b[0]), "r"(b[1]));
}

__device__ __forceinline__ void f2split(float x, __half& hi, __half& lo) {
    hi = __float2half_rn(x);
    lo = __float2half_rn(x - __half2float(hi));
}

// ---------------------------------------------------------------------------
// cp.async chunk loader: A is [MT x 512] (hi/lo), B is [128 x 512] (hi/lo).
// smem buffer layout (fp16 elems): Ahi[MT*40] Alo[MT*40] Bhi[128*40] Blo[128*40]
// ---------------------------------------------------------------------------
template<int MT>
__device__ __forceinline__ void load_chunk(
    uint32_t sbase,   // byte addr of buffer start
    const __half* __restrict__ Ah, const __half* __restrict__ Al,
    const __half* __restrict__ Bh, const __half* __restrict__ Bl,
    int kc, int tid)
{
    #pragma unroll
    for (int u = tid; u < MT * 4; u += 256) {
        int r = u >> 2, c = (u & 3) * 8;
        uint32_t d = sbase + (uint32_t)(r * LDS_ + c) * 2;
        const size_t go = (size_t)r * KDIM + kc + c;
        cp16(d,                       Ah + go);
        cp16(d + MT * LDS_ * 2,       Al + go);
    }
    #pragma unroll
    for (int u = tid; u < 128 * 4; u += 256) {
        int r = u >> 2, c = (u & 3) * 8;
        uint32_t d = sbase + (uint32_t)(2 * MT * LDS_ + r * LDS_ + c) * 2;
        const size_t go = (size_t)r * KDIM + kc + c;
        cp16(d,                       Bh + go);
        cp16(d + 128 * LDS_ * 2,      Bl + go);
    }
}

// ---------------------------------------------------------------------------
// Shared mainloop. MI = m16-frags per warp (2 -> MT=64, 4 -> MT=128).
// 8 warps: 2 (m) x 4 (n); warp tile = (MI*16) x 32. N-tile fixed at 128.
// acc[mi][n8][4], fp32. Split-precision: hi*hi + hi*lo + lo*hi.
// ---------------------------------------------------------------------------
template<int MI>
__device__ __forceinline__ void mma_mainloop(
    uint32_t sb,
    const __half* __restrict__ Ah, const __half* __restrict__ Al,
    const __half* __restrict__ Bh, const __half* __restrict__ Bl,
    float acc[MI][4][4], int tid)
{
    const int MT = MI * 32;                       // 2 warps along m
    const int STAGE_B = (2 * MT * LDS_ + 2 * 128 * LDS_) * 2;
    const int lane = tid & 31, wid = tid >> 5;
    const int mw = (wid & 1) * (MI * 16);
    const int nw = (wid >> 1) * 32;

    // ldmatrix per-lane row/col mapping
    const int a_row = mw + (lane & 15);
    const int a_col = (lane >> 4) * 8;
    const int b_row = nw + ((lane >> 4) << 3) + (lane & 7);
    const int b_col = ((lane >> 3) & 1) * 8;

    load_chunk<MT>(sb, Ah, Al, Bh, Bl, 0, tid);
    cp_commit();

    #pragma unroll 1
    for (int c = 0; c < NCHUNK; ++c) {
        const int buf = c & 1;
        if (c + 1 < NCHUNK) {
            load_chunk<MT>(sb + (buf ^ 1) * STAGE_B, Ah, Al, Bh, Bl, (c + 1) * CH, tid);
            cp_commit();
            cp_wait<1>();
        } else {
            cp_wait<0>();
        }
        __syncthreads();

        const uint32_t base = sb + buf * STAGE_B;
        #pragma unroll
        for (int kk = 0; kk < CH; kk += 16) {
            uint32_t ra[MI][4], rl[MI][4];
            uint32_t rbh[2][4], rbl[2][4];
            #pragma unroll
            for (int mi = 0; mi < MI; ++mi) {
                uint32_t aaddr = base + (uint32_t)((a_row + mi * 16) * LDS_ + kk + a_col) * 2;
                ldm4(aaddr, ra[mi]);
                ldm4(aaddr + MT * LDS_ * 2, rl[mi]);
            }
            #pragma unroll
            for (int nj = 0; nj < 2; ++nj) {
                uint32_t baddr = base + (uint32_t)(2 * MT * LDS_ + (b_row + nj * 16) * LDS_ + kk + b_col) * 2;
                ldm4(baddr, rbh[nj]);
                ldm4(baddr + 128 * LDS_ * 2, rbl[nj]);
            }
            #pragma unroll
            for (int mi = 0; mi < MI; ++mi) {
                #pragma unroll
                for (int b8 = 0; b8 < 4; ++b8) {
                    const uint32_t* bh = &rbh[b8 >> 1][(b8 & 1) * 2];
                    const uint32_t* bl = &rbl[b8 >> 1][(b8 & 1) * 2];
                    mma16816(acc[mi][b8], ra[mi], bh);   // hi*hi
                    mma16816(acc[mi][b8], ra[mi], bl);   // hi*lo
                    mma16816(acc[mi][b8], rl[mi], bh);   // lo*hi
                }
            }
        }
        __syncthreads();   // buffer reuse guard
    }
}

// ---------------------------------------------------------------------------
// Setup kernels
// ---------------------------------------------------------------------------
__global__ void init_state_kernel() {
    int idx = blockIdx.x * blockDim.x + threadIdx.x;
    if (idx < N_ * H_) {
        g_h_hi[0][idx] = __float2half_rn(0.0f);
        g_h_lo[0][idx] = __float2half_rn(0.0f);
        g_c[idx] = 0.0f;
    }
}

__global__ void conv_x_kernel(const float* __restrict__ X) {
    size_t base = ((size_t)blockIdx.x * blockDim.x + threadIdx.x) * 4;
    if (base < (size_t)M_ * KDIM) {
        float4 v = *(const float4*)(X + base);
        __half h0, l0, h1, l1, h2, l2, h3, l3;
        f2split(v.x, h0, l0); f2split(v.y, h1, l1);
        f2split(v.z, h2, l2); f2split(v.w, h3, l3);
        gX_hi[base + 0] = h0; gX_hi[base + 1] = h1; gX_hi[base + 2] = h2; gX_hi[base + 3] = h3;
        gX_lo[base + 0] = l0; gX_lo[base + 1] = l1; gX_lo[base + 2] = l2; gX_lo[base + 3] = l3;
    }
}

__global__ void conv_w_kernel(const float* __restrict__ Wih,
                              const float* __restrict__ Whh,
                              const float* __restrict__ bih,
                              const float* __restrict__ bhh) {
    int jp = blockIdx.x;                 // interleaved dst row 0..2047
    int gate = jp & 3, h = jp >> 2;
    int j = gate * H_ + h;               // source row
    const float* si = Wih + (size_t)j * KDIM;
    const float* sh = Whh + (size_t)j * KDIM;
    for (int k = threadIdx.x; k < KDIM; k += blockDim.x) {
        __half hi, lo;
        f2split(si[k], hi, lo);
        gWih_hi[(size_t)jp * KDIM + k] = hi; gWih_lo[(size_t)jp * KDIM + k] = lo;
        f2split(sh[k], hi, lo);
        gWhh_hi[(size_t)jp * KDIM + k] = hi; gWhh_lo[(size_t)jp * KDIM + k] = lo;
    }
    if (threadIdx.x == 0) g_biasI[jp] = bih[j] + bhh[j];
}

// ---------------------------------------------------------------------------
// x_gates GEMM: 128x128 tile, grid (16, 500).
// ---------------------------------------------------------------------------
#define XG_SMEM  ((2*128*LDS_ + 2*128*LDS_) * 2 * 2)     // 81920 B

__global__ __launch_bounds__(256, 1)
void xg_mma_kernel() {
    extern __shared__ __half smem[];
    const uint32_t sb = smem_u32_of(smem);
    __shared__ float bias_s[128];
    const int tid = threadIdx.x;
    const int j0 = blockIdx.x * 128;
    const int m0 = blockIdx.y * 128;
    if (tid < 128) bias_s[tid] = g_biasI[j0 + tid];

    float acc[4][4][4];
    #pragma unroll
    for (int a = 0; a < 4; ++a)
        #pragma unroll
        for (int b = 0; b < 4; ++b)
            #pragma unroll
            for (int d = 0; d < 4; ++d) acc[a][b][d] = 0.0f;

    mma_mainloop<4>(sb,
        gX_hi   + (size_t)m0 * KDIM, gX_lo   + (size_t)m0 * KDIM,
        gWih_hi + (size_t)j0 * KDIM, gWih_lo + (size_t)j0 * KDIM,
        acc, tid);

    const int lane = tid & 31, wid = tid >> 5;
    const int mw = (wid & 1) * 64, nw = (wid >> 1) * 32;
    #pragma unroll
    for (int mi = 0; mi < 4; ++mi) {
        #pragma unroll
        for (int h2 = 0; h2 < 2; ++h2) {
            const int r = m0 + mw + mi * 16 + (lane >> 2) + h2 * 8;
            float* dst = g_xg + (size_t)r * G_ + j0;
            #pragma unroll
            for (int ni = 0; ni < 4; ++ni) {
                const int cc = nw + ni * 8 + (lane & 3) * 2;
                float2 v = make_float2(acc[mi][ni][h2 * 2 + 0] + bias_s[cc],
                                       acc[mi][ni][h2 * 2 + 1] + bias_s[cc + 1]);
                *(float2*)(dst + cc) = v;
            }
        }
    }
}

// ---------------------------------------------------------------------------
// Recurrent step: 64x128 tile (= 64 seqs x 32 h x 4 gates), grid (16, 10),
// fused cell update via smem-staged C.
// ---------------------------------------------------------------------------
#define STEP_SMEM ((2*64*LDS_ + 2*128*LDS_) * 2 * 2)     // 61440 B

__global__ __launch_bounds__(256, 2)
void step_mma_kernel(float* __restrict__ out, int t) {
    extern __shared__ __half smem[];
    const uint32_t sb = smem_u32_of(smem);
    const int tid = threadIdx.x;
    const int j0 = blockIdx.x * 128;     // interleaved gate-col base
    const int hb = blockIdx.x * 32;      // h-column base
    const int n0 = blockIdx.y * 64;      // sequence-row base
    const int cur = t & 1, nxt = (t + 1) & 1;

    float acc[2][4][4];
    #pragma unroll
    for (int a = 0; a < 2; ++a)
        #pragma unroll
        for (int b = 0; b < 4; ++b)
            #pragma unroll
            for (int d = 0; d < 4; ++d) acc[a][b][d] = 0.0f;

    mma_mainloop<2>(sb,
        g_h_hi[cur] + (size_t)n0 * H_, g_h_lo[cur] + (size_t)n0 * H_,
        gWhh_hi + (size_t)j0 * KDIM,   gWhh_lo + (size_t)j0 * KDIM,
        acc, tid);

    // stage C tile [64][128] (stride 132) in smem
    float* Cs = (float*)smem;
    const int lane = tid & 31, wid = tid >> 5;
    const int mw = (wid & 1) * 32, nw = (wid >> 1) * 32;
    #pragma unroll
    for (int mi = 0; mi < 2; ++mi) {
        #pragma unroll
        for (int ni = 0; ni < 4; ++ni) {
            const int r = mw + mi * 16 + (lane >> 2);
            const int c = nw + ni * 8 + (lane & 3) * 2;
            *(float2*)&Cs[r * 132 + c]       = make_float2(acc[mi][ni][0], acc[mi][ni][1]);
            *(float2*)&Cs[(r + 8) * 132 + c] = make_float2(acc[mi][ni][2], acc[mi][ni][3]);
        }
    }
    __syncthreads();

    // fused LSTM cell update: thread u handles h-lane (u&31), rows (u>>5)+8e
    const bool last = (t == T_ - 1);
    const int hl = tid & 31;
    #pragma unroll
    for (int e = 0; e < 8; ++e) {
        const int nr = (tid >> 5) + e * 8;
        const int gn = n0 + nr;
        float4 cg = *(const float4*)&Cs[nr * 132 + hl * 4];
        float4 xv = *(const float4*)(g_xg + ((size_t)gn * T_ + t) * G_ + j0 + hl * 4);
        float ig = cg.x + xv.x, fg = cg.y + xv.y;
        float gg = cg.z + xv.z, og = cg.w + xv.w;

        float is = 1.0f / (1.0f + expf(-ig));
        float fs = 1.0f / (1.0f + expf(-fg));
        float gt = tanhf(gg);
        float os = 1.0f / (1.0f + expf(-og));

        const size_t ci = (size_t)gn * H_ + hb + hl;
        float c = fs * g_c[ci] + is * gt;
        g_c[ci] = c;
        float hv = os * tanhf(c);
        if (last) {
            out[ci] = hv;
        } else {
            __half hi, lo;
            f2split(hv, hi, lo);
            g_h_hi[nxt][ci] = hi;
            g_h_lo[nxt][ci] = lo;
        }
    }
}

// ---------------------------------------------------------------------------
// Launch
// ---------------------------------------------------------------------------
extern "C" void kernel_launch(void* const* d_in, const int* in_sizes, int n_in,
                              void* d_out, int out_size)
{
    const float* X   = (const float*)d_in[0];   // [B,Q,T,D] == [N*T, D]
    const float* Wih = (const float*)d_in[1];   // [4H, D]
    const float* Whh = (const float*)d_in[2];   // [4H, H]
    const float* bih = (const float*)d_in[3];   // [4H]
    const float* bhh = (const float*)d_in[4];   // [4H]
    float* out = (float*)d_out;                 // [B,Q,H] == [N, H]

    cudaFuncSetAttribute(xg_mma_kernel,   cudaFuncAttributeMaxDynamicSharedMemorySize, XG_SMEM);
    cudaFuncSetAttribute(step_mma_kernel, cudaFuncAttributeMaxDynamicSharedMemorySize, STEP_SMEM);

    init_state_kernel<<<(N_ * H_ + 255) / 256, 256>>>();
    conv_x_kernel<<<(int)(((size_t)M_ * KDIM / 4 + 255) / 256), 256>>>(X);
    conv_w_kernel<<<G_, 256>>>(Wih, Whh, bih, bhh);

    xg_mma_kernel<<<dim3(G_ / 128, M_ / 128), 256, XG_SMEM>>>();

    for (int t = 0; t < T_; ++t) {
        step_mma_kernel<<<dim3(G_ / 128, N_ / 64), 256, STEP_SMEM>>>(out, t);
    }
}